// round 3
// baseline (speedup 1.0000x reference)
#include <cuda_runtime.h>
#include <math.h>

#define Bx 4
#define Nn 2048
#define Mm 2048
#define Pp 2048
#define NSs 1024
#define NA (Bx*Nn)    // 8192 (pc1_0 flat)
#define NB (Bx*Mm)    // 8192 (pc2 flat)
#define NSA (Bx*NSs)  // 4096 (pc1_1 flat)
#define NC (Bx*Pp)    // 8192 (pc3/pc1_3 flat)

#define INF_BITS 0x7F7FFFFFu

// Scratch (device globals — no allocation allowed)
__device__ unsigned g_minA[NA];    // NN d2 of each pc1_0 point in pc2   (dist2 of main chamfer)
__device__ unsigned g_minB[NB];    // NN d2 of each pc2 point in pc1_0   (dist1 of main chamfer)
__device__ unsigned g_minSA[NSA];  // NN d2 of each pc1_1 point in pc2   (dist2 of seed chamfer)
__device__ unsigned g_minSB[NB];   // NN d2 of each pc2 point in pc1_1   (dist1 of seed chamfer)
__device__ unsigned g_minC[NC];    // per-(b,p): NN d2 of pc3[b,p] in pc2[b,:]
__device__ float    g_scalarC;     // conf_loss + 0.5*cd + seed_loss

// Selector resolved IN DEVICE CODE (host cannot take addresses of __device__ globals).
__device__ __forceinline__ unsigned* min_array(int sel) {
    switch (sel) {
        case 0: return g_minA;
        case 1: return g_minB;
        case 2: return g_minSA;
        case 3: return g_minSB;
        default: return g_minC;
    }
}

__global__ void init_kernel() {
    int i = blockIdx.x * blockDim.x + threadIdx.x;
    if (i < NA)  g_minA[i]  = INF_BITS;
    if (i < NB)  { g_minB[i] = INF_BITS; g_minSB[i] = INF_BITS; }
    if (i < NSA) g_minSA[i] = INF_BITS;
    if (i < NC)  g_minC[i]  = INF_BITS;
}

// For each query point, min squared distance to refs in [blockIdx.y*nrChunk, +nrChunk).
// Batched via blockIdx.z (Q/R/out advance by nq*3 / nr*3 / nq per batch).
// Requires: nq % 256 == 0, nrChunk % 256 == 0.
__global__ void __launch_bounds__(256) nn_kernel(
    const float* __restrict__ Q, int nq,
    const float* __restrict__ R, int nr,
    int outSel, int nrChunk)
{
    __shared__ float4 sR[256];  // x, y, z, |r|^2
    int z = blockIdx.z;
    Q += (size_t)z * nq * 3;
    R += (size_t)z * nr * 3;
    unsigned* om = min_array(outSel) + (size_t)z * nq;

    int q = blockIdx.x * 256 + threadIdx.x;
    float qx = Q[q * 3 + 0];
    float qy = Q[q * 3 + 1];
    float qz = Q[q * 3 + 2];
    float qq = qx * qx + qy * qy + qz * qz;

    int r0 = blockIdx.y * nrChunk;
    float m0 = 3.0e38f, m1 = 3.0e38f, m2 = 3.0e38f, m3 = 3.0e38f;

    for (int base = r0; base < r0 + nrChunk; base += 256) {
        __syncthreads();
        {
            int t = threadIdx.x;
            float rx = R[(base + t) * 3 + 0];
            float ry = R[(base + t) * 3 + 1];
            float rz = R[(base + t) * 3 + 2];
            sR[t] = make_float4(rx, ry, rz, rx * rx + ry * ry + rz * rz);
        }
        __syncthreads();

        #pragma unroll 8
        for (int j = 0; j < 256; j += 4) {
            float4 r0v = sR[j + 0];
            float4 r1v = sR[j + 1];
            float4 r2v = sR[j + 2];
            float4 r3v = sR[j + 3];
            float d0 = fmaf(-2.0f, fmaf(qx, r0v.x, fmaf(qy, r0v.y, qz * r0v.z)), qq + r0v.w);
            float d1 = fmaf(-2.0f, fmaf(qx, r1v.x, fmaf(qy, r1v.y, qz * r1v.z)), qq + r1v.w);
            float d2 = fmaf(-2.0f, fmaf(qx, r2v.x, fmaf(qy, r2v.y, qz * r2v.z)), qq + r2v.w);
            float d3 = fmaf(-2.0f, fmaf(qx, r3v.x, fmaf(qy, r3v.y, qz * r3v.z)), qq + r3v.w);
            m0 = fminf(m0, d0);
            m1 = fminf(m1, d1);
            m2 = fminf(m2, d2);
            m3 = fminf(m3, d3);
        }
    }
    m0 = fminf(fminf(m0, m1), fminf(m2, m3));
    m0 = fmaxf(m0, 0.0f);
    atomicMin(&om[q], __float_as_uint(m0));
}

// Single block, deterministic tree reduction of all scalar terms.
__global__ void __launch_bounds__(1024) reduce_kernel(const float* __restrict__ pc1_3) {
    __shared__ float sh[1024];
    int t = threadIdx.x;
    float sA = 0.f, sB = 0.f, sSA = 0.f, sSB = 0.f, sC = 0.f;

    for (int i = t; i < NA; i += 1024)  sA  += sqrtf(__uint_as_float(g_minA[i]));
    for (int i = t; i < NB; i += 1024)  sB  += sqrtf(__uint_as_float(g_minB[i]));
    for (int i = t; i < NB; i += 1024)  sSB += sqrtf(__uint_as_float(g_minSB[i]));
    for (int i = t; i < NSA; i += 1024) sSA += sqrtf(__uint_as_float(g_minSA[i]));
    for (int i = t; i < NC; i += 1024) {
        float d = sqrtf(__uint_as_float(g_minC[i]));
        float df = pc1_3[i] - expf(-d);
        sC += df * df;
    }

    float vals[5] = {sA, sB, sSA, sSB, sC};
    float res[5];
    #pragma unroll
    for (int k = 0; k < 5; k++) {
        sh[t] = vals[k];
        __syncthreads();
        for (int s = 512; s > 0; s >>= 1) {
            if (t < s) sh[t] += sh[t + s];
            __syncthreads();
        }
        res[k] = sh[0];
        __syncthreads();
    }
    if (t == 0) {
        float cd   = res[0] / (float)NA + res[1] / (float)NB;   // mean(dist2) + mean(dist1)
        float seed = res[2] / (float)NSA + res[3] / (float)NB;
        float conf = res[4] / (float)NC;
        g_scalarC = conf + 0.5f * cd + seed;
    }
}

// out[b,n,m] = C + 0.5*dist(pc1_0[b,n], pc2[b,m])
// grid: (M/128, N/8, B), block 256. Each thread: 1 row, 4 consecutive m (float4 store).
__global__ void __launch_bounds__(256) emd_kernel(
    const float* __restrict__ pc1_0, const float* __restrict__ pc2,
    float* __restrict__ out)
{
    __shared__ float4 sP[128];
    int b = blockIdx.z;
    const float* Qb = pc1_0 + (size_t)b * Nn * 3;
    const float* Rb = pc2   + (size_t)b * Mm * 3;
    int tid = threadIdx.x;

    if (tid < 128) {
        int m = blockIdx.x * 128 + tid;
        float rx = Rb[m * 3 + 0];
        float ry = Rb[m * 3 + 1];
        float rz = Rb[m * 3 + 2];
        sP[tid] = make_float4(rx, ry, rz, rx * rx + ry * ry + rz * rz);
    }
    __syncthreads();

    float C = g_scalarC;
    int row  = blockIdx.y * 8 + (tid >> 5);
    int lane = tid & 31;

    float qx = Qb[row * 3 + 0];
    float qy = Qb[row * 3 + 1];
    float qz = Qb[row * 3 + 2];
    float qq = qx * qx + qy * qy + qz * qz;

    int ml = lane * 4;
    float4 o;
    {
        float4 r0v = sP[ml + 0];
        float4 r1v = sP[ml + 1];
        float4 r2v = sP[ml + 2];
        float4 r3v = sP[ml + 3];
        float d0 = fmaf(-2.0f, fmaf(qx, r0v.x, fmaf(qy, r0v.y, qz * r0v.z)), qq + r0v.w);
        float d1 = fmaf(-2.0f, fmaf(qx, r1v.x, fmaf(qy, r1v.y, qz * r1v.z)), qq + r1v.w);
        float d2 = fmaf(-2.0f, fmaf(qx, r2v.x, fmaf(qy, r2v.y, qz * r2v.z)), qq + r2v.w);
        float d3 = fmaf(-2.0f, fmaf(qx, r3v.x, fmaf(qy, r3v.y, qz * r3v.z)), qq + r3v.w);
        o.x = fmaf(0.5f, sqrtf(fmaxf(d0, 0.0f)), C);
        o.y = fmaf(0.5f, sqrtf(fmaxf(d1, 0.0f)), C);
        o.z = fmaf(0.5f, sqrtf(fmaxf(d2, 0.0f)), C);
        o.w = fmaf(0.5f, sqrtf(fmaxf(d3, 0.0f)), C);
    }
    float* op = out + ((size_t)(b * Nn + row)) * Mm + blockIdx.x * 128 + ml;
    *reinterpret_cast<float4*>(op) = o;
}

extern "C" void kernel_launch(void* const* d_in, const int* in_sizes, int n_in,
                              void* d_out, int out_size) {
    const float* pc1_0 = (const float*)d_in[0];  // [4,2048,3]
    const float* pc1_1 = (const float*)d_in[1];  // [4,1024,3]
    const float* pc1_3 = (const float*)d_in[2];  // [4,2048,1]
    const float* pc2   = (const float*)d_in[3];  // [4,2048,3]
    const float* pc3   = (const float*)d_in[4];  // [4,2048,3]
    float* out = (float*)d_out;                  // [4,2048,2048]

    init_kernel<<<32, 256>>>();

    // Main chamfer (flattened across batch):
    nn_kernel<<<dim3(NA / 256, 4, 1), 256>>>(pc1_0, NA, pc2,   NB,  0, 2048);
    nn_kernel<<<dim3(NB / 256, 4, 1), 256>>>(pc2,   NB, pc1_0, NA,  1, 2048);
    // Seed chamfer:
    nn_kernel<<<dim3(NSA / 256, 4, 1), 256>>>(pc1_1, NSA, pc2,   NB,  2, 2048);
    nn_kernel<<<dim3(NB / 256, 2, 1), 256>>>(pc2,   NB,  pc1_1, NSA, 3, 2048);
    // Confidence NN (per-batch):
    nn_kernel<<<dim3(Pp / 256, 2, Bx), 256>>>(pc3, Pp, pc2, Mm, 4, 1024);

    reduce_kernel<<<1, 1024>>>(pc1_3);

    emd_kernel<<<dim3(Mm / 128, Nn / 8, Bx), 256>>>(pc1_0, pc2, out);
}

// round 4
// speedup vs baseline: 1.5196x; 1.5196x over previous
#include <cuda_runtime.h>
#include <math.h>

#define Bx 4
#define Nn 2048
#define Mm 2048
#define Pp 2048
#define NSs 1024
#define NA (Bx*Nn)    // 8192 (pc1_0 flat)
#define NB (Bx*Mm)    // 8192 (pc2 flat)
#define NSA (Bx*NSs)  // 4096 (pc1_1 flat)
#define NC (Bx*Pp)    // 8192 (pc3/pc1_3 flat)

#define INF_BITS 0x7F7FFFFFu
#define RC 1024   // ref chunk per block

// Scratch (device globals — no allocation allowed)
__device__ unsigned g_minA[NA];    // NN d2' of each pc1_0 point in pc2 (d2' = d2 - qq, min-shifted)
__device__ unsigned g_minB[NB];
__device__ unsigned g_minSA[NSA];
__device__ unsigned g_minSB[NB];
__device__ unsigned g_minC[NC];
__device__ float    g_scalarC;

__global__ void init_kernel() {
    int i = blockIdx.x * blockDim.x + threadIdx.x;
    if (i < NA)  g_minA[i]  = INF_BITS;
    if (i < NB)  { g_minB[i] = INF_BITS; g_minSB[i] = INF_BITS; }
    if (i < NSA) g_minSA[i] = INF_BITS;
    if (i < NC)  g_minC[i]  = INF_BITS;
}

// All 5 NN tasks in one launch. Every block: 256 queries x 1024 refs.
// Block map (832 total):
//   [0,256):   A  pc1_0(8192) vs pc2(8192)   qb=bi>>3, rc=bi&7
//   [256,512): B  pc2(8192)   vs pc1_0(8192)
//   [512,640): SA pc1_1(4096) vs pc2(8192)
//   [640,768): SB pc2(8192)   vs pc1_1(4096) qb=bi>>2, rc=bi&3
//   [768,832): C  per-batch pc3(2048) vs pc2(2048): b=bi>>4, qb=(bi&15)>>1, rc=bi&1
__global__ void __launch_bounds__(256) nn_mega(
    const float* __restrict__ pc1_0, const float* __restrict__ pc1_1,
    const float* __restrict__ pc2,   const float* __restrict__ pc3)
{
    __shared__ float4 sR[RC];  // (-2x, -2y, -2z, |r|^2)
    const float* Q; const float* R; unsigned* om;
    int qb, rc;
    int bi = blockIdx.x;
    if (bi < 256)      { Q = pc1_0; R = pc2;   om = g_minA;  qb = bi >> 3; rc = bi & 7; }
    else if (bi < 512) { bi -= 256; Q = pc2;   R = pc1_0; om = g_minB;  qb = bi >> 3; rc = bi & 7; }
    else if (bi < 640) { bi -= 512; Q = pc1_1; R = pc2;   om = g_minSA; qb = bi >> 3; rc = bi & 7; }
    else if (bi < 768) { bi -= 640; Q = pc2;   R = pc1_1; om = g_minSB; qb = bi >> 2; rc = bi & 3; }
    else { bi -= 768; int b = bi >> 4; int rem = bi & 15; qb = rem >> 1; rc = rem & 1;
           Q = pc3 + b * Pp * 3; R = pc2 + b * Mm * 3; om = g_minC + b * Pp; }

    // Stage 1024 refs into smem, pre-scaled by -2, with |r|^2.
    for (int t = threadIdx.x; t < RC; t += 256) {
        int r = rc * RC + t;
        float rx = R[r * 3 + 0];
        float ry = R[r * 3 + 1];
        float rz = R[r * 3 + 2];
        sR[t] = make_float4(-2.0f * rx, -2.0f * ry, -2.0f * rz,
                            rx * rx + ry * ry + rz * rz);
    }

    int q = qb * 256 + threadIdx.x;
    float qx = Q[q * 3 + 0];
    float qy = Q[q * 3 + 1];
    float qz = Q[q * 3 + 2];
    float qq = qx * qx + qy * qy + qz * qz;

    __syncthreads();

    float m0 = 3.0e38f, m1 = 3.0e38f, m2 = 3.0e38f, m3 = 3.0e38f;
    #pragma unroll 8
    for (int j = 0; j < RC; j += 4) {
        float4 a = sR[j + 0];
        float4 b = sR[j + 1];
        float4 c = sR[j + 2];
        float4 e = sR[j + 3];
        // d' = |r|^2 - 2 q.r  (qq added after the min)
        float d0 = fmaf(qx, a.x, fmaf(qy, a.y, fmaf(qz, a.z, a.w)));
        float d1 = fmaf(qx, b.x, fmaf(qy, b.y, fmaf(qz, b.z, b.w)));
        float d2 = fmaf(qx, c.x, fmaf(qy, c.y, fmaf(qz, c.z, c.w)));
        float d3 = fmaf(qx, e.x, fmaf(qy, e.y, fmaf(qz, e.z, e.w)));
        m0 = fminf(m0, d0);
        m1 = fminf(m1, d1);
        m2 = fminf(m2, d2);
        m3 = fminf(m3, d3);
    }
    m0 = fminf(fminf(m0, m1), fminf(m2, m3));
    m0 = fmaxf(m0 + qq, 0.0f);   // shift back, clamp
    atomicMin(&om[q], __float_as_uint(m0));
}

// Single block, one deterministic weighted tree reduction.
__global__ void __launch_bounds__(1024) reduce_kernel(const float* __restrict__ pc1_3) {
    __shared__ float sh[1024];
    int t = threadIdx.x;
    float acc = 0.f;

    const float wA  = 0.5f / (float)NA;
    const float wB  = 0.5f / (float)NB;
    const float wSA = 1.0f / (float)NSA;
    const float wSB = 1.0f / (float)NB;
    const float wC  = 1.0f / (float)NC;

    for (int i = t; i < NA; i += 1024)  acc += wA  * sqrtf(__uint_as_float(g_minA[i]));
    for (int i = t; i < NB; i += 1024)  acc += wB  * sqrtf(__uint_as_float(g_minB[i]));
    for (int i = t; i < NB; i += 1024)  acc += wSB * sqrtf(__uint_as_float(g_minSB[i]));
    for (int i = t; i < NSA; i += 1024) acc += wSA * sqrtf(__uint_as_float(g_minSA[i]));
    for (int i = t; i < NC; i += 1024) {
        float d = sqrtf(__uint_as_float(g_minC[i]));
        float df = pc1_3[i] - expf(-d);
        acc += wC * df * df;
    }

    sh[t] = acc;
    __syncthreads();
    for (int s = 512; s > 0; s >>= 1) {
        if (t < s) sh[t] += sh[t + s];
        __syncthreads();
    }
    if (t == 0) g_scalarC = sh[0];
}

// out[b,n,m] = C + 0.5*dist(pc1_0[b,n], pc2[b,m])
// grid: (M/128, N/8, B), block 256. Each thread: 1 row, 4 consecutive m (float4 store).
__global__ void __launch_bounds__(256) emd_kernel(
    const float* __restrict__ pc1_0, const float* __restrict__ pc2,
    float* __restrict__ out)
{
    __shared__ float4 sP[128];  // (-2x,-2y,-2z,|r|^2)
    int b = blockIdx.z;
    const float* Qb = pc1_0 + (size_t)b * Nn * 3;
    const float* Rb = pc2   + (size_t)b * Mm * 3;
    int tid = threadIdx.x;

    if (tid < 128) {
        int m = blockIdx.x * 128 + tid;
        float rx = Rb[m * 3 + 0];
        float ry = Rb[m * 3 + 1];
        float rz = Rb[m * 3 + 2];
        sP[tid] = make_float4(-2.0f * rx, -2.0f * ry, -2.0f * rz,
                              rx * rx + ry * ry + rz * rz);
    }
    __syncthreads();

    float C = g_scalarC;
    int row  = blockIdx.y * 8 + (tid >> 5);
    int lane = tid & 31;

    float qx = Qb[row * 3 + 0];
    float qy = Qb[row * 3 + 1];
    float qz = Qb[row * 3 + 2];
    float qq = qx * qx + qy * qy + qz * qz;

    int ml = lane * 4;
    float4 o;
    {
        float4 a = sP[ml + 0];
        float4 bb = sP[ml + 1];
        float4 c = sP[ml + 2];
        float4 e = sP[ml + 3];
        float d0 = qq + fmaf(qx, a.x,  fmaf(qy, a.y,  fmaf(qz, a.z,  a.w)));
        float d1 = qq + fmaf(qx, bb.x, fmaf(qy, bb.y, fmaf(qz, bb.z, bb.w)));
        float d2 = qq + fmaf(qx, c.x,  fmaf(qy, c.y,  fmaf(qz, c.z,  c.w)));
        float d3 = qq + fmaf(qx, e.x,  fmaf(qy, e.y,  fmaf(qz, e.z,  e.w)));
        o.x = fmaf(0.5f, sqrtf(fmaxf(d0, 0.0f)), C);
        o.y = fmaf(0.5f, sqrtf(fmaxf(d1, 0.0f)), C);
        o.z = fmaf(0.5f, sqrtf(fmaxf(d2, 0.0f)), C);
        o.w = fmaf(0.5f, sqrtf(fmaxf(d3, 0.0f)), C);
    }
    float* op = out + ((size_t)(b * Nn + row)) * Mm + blockIdx.x * 128 + ml;
    *reinterpret_cast<float4*>(op) = o;
}

extern "C" void kernel_launch(void* const* d_in, const int* in_sizes, int n_in,
                              void* d_out, int out_size) {
    const float* pc1_0 = (const float*)d_in[0];  // [4,2048,3]
    const float* pc1_1 = (const float*)d_in[1];  // [4,1024,3]
    const float* pc1_3 = (const float*)d_in[2];  // [4,2048,1]
    const float* pc2   = (const float*)d_in[3];  // [4,2048,3]
    const float* pc3   = (const float*)d_in[4];  // [4,2048,3]
    float* out = (float*)d_out;                  // [4,2048,2048]

    init_kernel<<<32, 256>>>();
    nn_mega<<<832, 256>>>(pc1_0, pc1_1, pc2, pc3);
    reduce_kernel<<<1, 1024>>>(pc1_3);
    emd_kernel<<<dim3(Mm / 128, Nn / 8, Bx), 256>>>(pc1_0, pc2, out);
}

// round 7
// speedup vs baseline: 1.9890x; 1.3089x over previous
#include <cuda_runtime.h>
#include <math.h>

#define Bx 4
#define Nn 2048
#define Mm 2048
#define Pp 2048
#define NSs 1024
#define NA (Bx*Nn)    // 8192 (pc1_0 flat)
#define NB (Bx*Mm)    // 8192 (pc2 flat)
#define NSA (Bx*NSs)  // 4096 (pc1_1 flat)
#define NC (Bx*Pp)    // 8192 (pc3/pc1_3 flat)

#define INF_BITS 0x7F7FFFFFu
#define RC 1024   // refs per block chunk

typedef unsigned long long ull;

// Scratch (device globals — no allocation allowed)
__device__ unsigned g_minA[NA];
__device__ unsigned g_minB[NB];
__device__ unsigned g_minSA[NSA];
__device__ unsigned g_minSB[NB];
__device__ unsigned g_minC[NC];
__device__ float    g_scalarC;

__global__ void init_kernel() {
    int i = blockIdx.x * blockDim.x + threadIdx.x;
    if (i < NA)  g_minA[i]  = INF_BITS;
    if (i < NB)  { g_minB[i] = INF_BITS; g_minSB[i] = INF_BITS; }
    if (i < NSA) g_minSA[i] = INF_BITS;
    if (i < NC)  g_minC[i]  = INF_BITS;
}

__device__ __forceinline__ ull pack2(float lo, float hi) {
    ull r;
    asm("mov.b64 %0, {%1, %2};" : "=l"(r) : "f"(lo), "f"(hi));
    return r;
}
__device__ __forceinline__ void unpack2(ull v, float& lo, float& hi) {
    asm("mov.b64 {%0, %1}, %2;" : "=f"(lo), "=f"(hi) : "l"(v));
}
__device__ __forceinline__ ull ffma2(ull a, ull b, ull c) {
    ull d;
    asm("fma.rn.f32x2 %0, %1, %2, %3;" : "=l"(d) : "l"(a), "l"(b), "l"(c));
    return d;
}

// All 5 NN tasks in one launch. Every block: 512 queries (2/thread, packed f32x2)
// x 1024 refs. Block map (416 total):
//   [0,128):   A  pc1_0(8192) vs pc2(8192)   qb=bi>>3 (16), rc=bi&7
//   [128,256): B  pc2(8192)   vs pc1_0(8192)
//   [256,320): SA pc1_1(4096) vs pc2(8192)   qb=bi>>3 (8),  rc=bi&7
//   [320,384): SB pc2(8192)   vs pc1_1(4096) qb=bi>>2 (16), rc=bi&3
//   [384,416): C  per-batch pc3(2048) vs pc2(2048): b=bi>>3, qb=(bi&7)>>1, rc=bi&1
__global__ void __launch_bounds__(256) nn_mega(
    const float* __restrict__ pc1_0, const float* __restrict__ pc1_1,
    const float* __restrict__ pc2,   const float* __restrict__ pc3)
{
    // refs duplicated into both f32x2 halves:
    // sA[j] = { (-2x,-2x), (-2y,-2y) }, sB[j] = { (-2z,-2z), (w,w) }
    __shared__ ulonglong2 sA[RC];
    __shared__ ulonglong2 sB[RC];

    const float* Q; const float* R; unsigned* om;
    int qb, rc;
    int bi = blockIdx.x;
    if (bi < 128)      {            Q = pc1_0; R = pc2;   om = g_minA;  qb = bi >> 3; rc = bi & 7; }
    else if (bi < 256) { bi -= 128; Q = pc2;   R = pc1_0; om = g_minB;  qb = bi >> 3; rc = bi & 7; }
    else if (bi < 320) { bi -= 256; Q = pc1_1; R = pc2;   om = g_minSA; qb = bi >> 3; rc = bi & 7; }
    else if (bi < 384) { bi -= 320; Q = pc2;   R = pc1_1; om = g_minSB; qb = bi >> 2; rc = bi & 3; }
    else { bi -= 384; int b = bi >> 3; int rem = bi & 7; qb = rem >> 1; rc = rem & 1;
           Q = pc3 + b * Pp * 3; R = pc2 + b * Mm * 3; om = g_minC + b * Pp; }

    for (int t = threadIdx.x; t < RC; t += 256) {
        int r = rc * RC + t;
        float rx = R[r * 3 + 0];
        float ry = R[r * 3 + 1];
        float rz = R[r * 3 + 2];
        float w  = rx * rx + ry * ry + rz * rz;
        ulonglong2 a, bb;
        a.x  = pack2(-2.0f * rx, -2.0f * rx);
        a.y  = pack2(-2.0f * ry, -2.0f * ry);
        bb.x = pack2(-2.0f * rz, -2.0f * rz);
        bb.y = pack2(w, w);
        sA[t] = a;
        sB[t] = bb;
    }

    int q0 = qb * 512 + threadIdx.x;
    int q1 = q0 + 256;
    float q0x = Q[q0 * 3 + 0], q0y = Q[q0 * 3 + 1], q0z = Q[q0 * 3 + 2];
    float q1x = Q[q1 * 3 + 0], q1y = Q[q1 * 3 + 1], q1z = Q[q1 * 3 + 2];
    float qq0 = q0x * q0x + q0y * q0y + q0z * q0z;
    float qq1 = q1x * q1x + q1y * q1y + q1z * q1z;
    ull qx01 = pack2(q0x, q1x);
    ull qy01 = pack2(q0y, q1y);
    ull qz01 = pack2(q0z, q1z);

    __syncthreads();

    // d' = w - 2 q.r  (query norm qq added after the min)
    float ma0 = 3.0e38f, ma1 = 3.0e38f, mb0 = 3.0e38f, mb1 = 3.0e38f;
    #pragma unroll 8
    for (int j = 0; j < RC; j += 2) {
        ulonglong2 a0 = sA[j],     b0 = sB[j];
        ulonglong2 a1 = sA[j + 1], b1 = sB[j + 1];
        ull t0 = ffma2(qx01, a0.x, ffma2(qy01, a0.y, ffma2(qz01, b0.x, b0.y)));
        ull t1 = ffma2(qx01, a1.x, ffma2(qy01, a1.y, ffma2(qz01, b1.x, b1.y)));
        float l0, h0, l1, h1;
        unpack2(t0, l0, h0);
        unpack2(t1, l1, h1);
        ma0 = fminf(ma0, l0);
        ma1 = fminf(ma1, h0);
        mb0 = fminf(mb0, l1);
        mb1 = fminf(mb1, h1);
    }
    float m_0 = fmaxf(fminf(ma0, mb0) + qq0, 0.0f);
    float m_1 = fmaxf(fminf(ma1, mb1) + qq1, 0.0f);
    atomicMin(&om[q0], __float_as_uint(m_0));
    atomicMin(&om[q1], __float_as_uint(m_1));
}

// Single block, one deterministic weighted tree reduction.
__global__ void __launch_bounds__(1024) reduce_kernel(const float* __restrict__ pc1_3) {
    __shared__ float sh[1024];
    int t = threadIdx.x;
    float acc = 0.f;

    const float wA  = 0.5f / (float)NA;
    const float wB  = 0.5f / (float)NB;
    const float wSA = 1.0f / (float)NSA;
    const float wSB = 1.0f / (float)NB;
    const float wC  = 1.0f / (float)NC;

    for (int i = t; i < NA; i += 1024)  acc += wA  * sqrtf(__uint_as_float(g_minA[i]));
    for (int i = t; i < NB; i += 1024)  acc += wB  * sqrtf(__uint_as_float(g_minB[i]));
    for (int i = t; i < NB; i += 1024)  acc += wSB * sqrtf(__uint_as_float(g_minSB[i]));
    for (int i = t; i < NSA; i += 1024) acc += wSA * sqrtf(__uint_as_float(g_minSA[i]));
    for (int i = t; i < NC; i += 1024) {
        float d = sqrtf(__uint_as_float(g_minC[i]));
        float df = pc1_3[i] - expf(-d);
        acc += wC * df * df;
    }

    sh[t] = acc;
    __syncthreads();
    for (int s = 512; s > 0; s >>= 1) {
        if (t < s) sh[t] += sh[t + s];
        __syncthreads();
    }
    if (t == 0) g_scalarC = sh[0];
}

// out[b,n,m] = C + 0.5*dist(pc1_0[b,n], pc2[b,m])
// Block tile: 64 rows x 128 cols, 256 threads; each thread 8 rows x 4 cols,
// refs held in registers (LDS amortized 8x). grid (16, 32, 4).
__global__ void __launch_bounds__(256) emd_kernel(
    const float* __restrict__ pc1_0, const float* __restrict__ pc2,
    float* __restrict__ out)
{
    __shared__ float4 sP[128];  // (-2x,-2y,-2z,|r|^2) per col
    __shared__ float4 sQ[64];   // (qx,qy,qz,qq) per row
    int b = blockIdx.z;
    const float* Qb = pc1_0 + (size_t)b * Nn * 3;
    const float* Rb = pc2   + (size_t)b * Mm * 3;
    int tid = threadIdx.x;

    if (tid < 128) {
        int m = blockIdx.x * 128 + tid;
        float rx = Rb[m * 3 + 0];
        float ry = Rb[m * 3 + 1];
        float rz = Rb[m * 3 + 2];
        sP[tid] = make_float4(-2.0f * rx, -2.0f * ry, -2.0f * rz,
                              rx * rx + ry * ry + rz * rz);
    } else if (tid < 192) {
        int r = tid - 128;
        int row = blockIdx.y * 64 + r;
        float qx = Qb[row * 3 + 0];
        float qy = Qb[row * 3 + 1];
        float qz = Qb[row * 3 + 2];
        sQ[r] = make_float4(qx, qy, qz, qx * qx + qy * qy + qz * qz);
    }
    __syncthreads();

    float C = g_scalarC;
    int warp = tid >> 5;
    int lane = tid & 31;
    int ml = lane * 4;

    float4 a  = sP[ml + 0];
    float4 bb = sP[ml + 1];
    float4 c  = sP[ml + 2];
    float4 e  = sP[ml + 3];

    size_t rowBase = ((size_t)(b * Nn) + blockIdx.y * 64 + warp * 8) * Mm
                     + blockIdx.x * 128 + ml;

    #pragma unroll 8
    for (int r = 0; r < 8; r++) {
        float4 qv = sQ[warp * 8 + r];  // warp-uniform broadcast
        float d0 = qv.w + fmaf(qv.x, a.x,  fmaf(qv.y, a.y,  fmaf(qv.z, a.z,  a.w)));
        float d1 = qv.w + fmaf(qv.x, bb.x, fmaf(qv.y, bb.y, fmaf(qv.z, bb.z, bb.w)));
        float d2 = qv.w + fmaf(qv.x, c.x,  fmaf(qv.y, c.y,  fmaf(qv.z, c.z,  c.w)));
        float d3 = qv.w + fmaf(qv.x, e.x,  fmaf(qv.y, e.y,  fmaf(qv.z, e.z,  e.w)));
        d0 = fmaxf(d0, 1e-30f);
        d1 = fmaxf(d1, 1e-30f);
        d2 = fmaxf(d2, 1e-30f);
        d3 = fmaxf(d3, 1e-30f);
        float4 o;
        o.x = fmaf(0.5f, d0 * rsqrtf(d0), C);
        o.y = fmaf(0.5f, d1 * rsqrtf(d1), C);
        o.z = fmaf(0.5f, d2 * rsqrtf(d2), C);
        o.w = fmaf(0.5f, d3 * rsqrtf(d3), C);
        *reinterpret_cast<float4*>(&out[rowBase + (size_t)r * Mm]) = o;
    }
}

extern "C" void kernel_launch(void* const* d_in, const int* in_sizes, int n_in,
                              void* d_out, int out_size) {
    const float* pc1_0 = (const float*)d_in[0];  // [4,2048,3]
    const float* pc1_1 = (const float*)d_in[1];  // [4,1024,3]
    const float* pc1_3 = (const float*)d_in[2];  // [4,2048,1]
    const float* pc2   = (const float*)d_in[3];  // [4,2048,3]
    const float* pc3   = (const float*)d_in[4];  // [4,2048,3]
    float* out = (float*)d_out;                  // [4,2048,2048]

    init_kernel<<<32, 256>>>();
    nn_mega<<<416, 256>>>(pc1_0, pc1_1, pc2, pc3);
    reduce_kernel<<<1, 1024>>>(pc1_3);
    emd_kernel<<<dim3(Mm / 128, Nn / 64, Bx), 256>>>(pc1_0, pc2, out);
}

// round 9
// speedup vs baseline: 2.0888x; 1.0502x over previous
#include <cuda_runtime.h>
#include <math.h>

#define Bx 4
#define Nn 2048
#define Mm 2048
#define Pp 2048
#define NSs 1024
#define NA (Bx*Nn)    // 8192 (pc1_0 flat)
#define NB (Bx*Mm)    // 8192 (pc2 flat)
#define NSA (Bx*NSs)  // 4096 (pc1_1 flat)
#define NC (Bx*Pp)    // 8192 (pc3/pc1_3 flat)

#define INF_BITS 0x7F7FFFFFu
#define RC 512   // refs per block chunk

typedef unsigned long long ull;

// Scratch (device globals — no allocation allowed)
__device__ unsigned g_minA[NA];
__device__ unsigned g_minB[NB];
__device__ unsigned g_minSA[NSA];
__device__ unsigned g_minSB[NB];
__device__ unsigned g_minC[NC];
__device__ float    g_scalarC;

__global__ void init_kernel() {
    int i = blockIdx.x * blockDim.x + threadIdx.x;
    if (i < NA)  g_minA[i]  = INF_BITS;
    if (i < NB)  { g_minB[i] = INF_BITS; g_minSB[i] = INF_BITS; }
    if (i < NSA) g_minSA[i] = INF_BITS;
    if (i < NC)  g_minC[i]  = INF_BITS;
}

__device__ __forceinline__ ull pack2(float lo, float hi) {
    ull r;
    asm("mov.b64 %0, {%1, %2};" : "=l"(r) : "f"(lo), "f"(hi));
    return r;
}
__device__ __forceinline__ void unpack2(ull v, float& lo, float& hi) {
    asm("mov.b64 {%0, %1}, %2;" : "=f"(lo), "=f"(hi) : "l"(v));
}
__device__ __forceinline__ ull ffma2(ull a, ull b, ull c) {
    ull d;
    asm("fma.rn.f32x2 %0, %1, %2, %3;" : "=l"(d) : "l"(a), "l"(b), "l"(c));
    return d;
}

// All 5 NN tasks in one launch. Every block: 2048 queries (8/thread, 4 packed
// f32x2 pairs) x 512 refs. Block map (208 total):
//   [0,64):    A  pc1_0(8192) vs pc2(8192)   qb=bi>>4, rc=bi&15
//   [64,128):  B  pc2(8192)   vs pc1_0(8192)
//   [128,160): SA pc1_1(4096) vs pc2(8192)   qb=bi>>4, rc=bi&15
//   [160,192): SB pc2(8192)   vs pc1_1(4096) qb=bi>>3, rc=bi&7
//   [192,208): C  per-batch pc3(2048) vs pc2(2048): b=bi>>2, qb=0, rc=bi&3
__global__ void __launch_bounds__(256) nn_mega(
    const float* __restrict__ pc1_0, const float* __restrict__ pc1_1,
    const float* __restrict__ pc2,   const float* __restrict__ pc3)
{
    // refs duplicated into both f32x2 halves:
    // sA[j] = { (-2x,-2x), (-2y,-2y) }, sB[j] = { (-2z,-2z), (w,w) }
    __shared__ ulonglong2 sA[RC];
    __shared__ ulonglong2 sB[RC];

    const float* Q; const float* R; unsigned* om;
    int qb, rc;
    int bi = blockIdx.x;
    if (bi < 64)       {            Q = pc1_0; R = pc2;   om = g_minA;  qb = bi >> 4; rc = bi & 15; }
    else if (bi < 128) { bi -= 64;  Q = pc2;   R = pc1_0; om = g_minB;  qb = bi >> 4; rc = bi & 15; }
    else if (bi < 160) { bi -= 128; Q = pc1_1; R = pc2;   om = g_minSA; qb = bi >> 4; rc = bi & 15; }
    else if (bi < 192) { bi -= 160; Q = pc2;   R = pc1_1; om = g_minSB; qb = bi >> 3; rc = bi & 7; }
    else { bi -= 192; int b = bi >> 2; qb = 0; rc = bi & 3;
           Q = pc3 + b * Pp * 3; R = pc2 + b * Mm * 3; om = g_minC + b * Pp; }

    // Stage 512 refs (2 per thread).
    for (int t = threadIdx.x; t < RC; t += 256) {
        int r = rc * RC + t;
        float rx = R[r * 3 + 0];
        float ry = R[r * 3 + 1];
        float rz = R[r * 3 + 2];
        float w  = rx * rx + ry * ry + rz * rz;
        ulonglong2 a, bb;
        a.x  = pack2(-2.0f * rx, -2.0f * rx);
        a.y  = pack2(-2.0f * ry, -2.0f * ry);
        bb.x = pack2(-2.0f * rz, -2.0f * rz);
        bb.y = pack2(w, w);
        sA[t] = a;
        sB[t] = bb;
    }

    // 8 queries per thread: q_i = qb*2048 + i*256 + tid  (coalesced).
    int q0 = qb * 2048 + threadIdx.x;
    float qx[8], qy[8], qz[8], qq[8];
    #pragma unroll
    for (int i = 0; i < 8; i++) {
        int q = q0 + i * 256;
        qx[i] = Q[q * 3 + 0];
        qy[i] = Q[q * 3 + 1];
        qz[i] = Q[q * 3 + 2];
        qq[i] = qx[i] * qx[i] + qy[i] * qy[i] + qz[i] * qz[i];
    }
    ull px[4], py[4], pz[4];
    #pragma unroll
    for (int p = 0; p < 4; p++) {
        px[p] = pack2(qx[2 * p], qx[2 * p + 1]);
        py[p] = pack2(qy[2 * p], qy[2 * p + 1]);
        pz[p] = pack2(qz[2 * p], qz[2 * p + 1]);
    }

    __syncthreads();

    // d' = w - 2 q.r  (query norm qq added after the min)
    float mn[8];
    #pragma unroll
    for (int i = 0; i < 8; i++) mn[i] = 3.0e38f;

    #pragma unroll 4
    for (int j = 0; j < RC; j++) {
        ulonglong2 a = sA[j];   // (xx, yy)
        ulonglong2 b = sB[j];   // (zz, ww)
        #pragma unroll
        for (int p = 0; p < 4; p++) {
            ull t = ffma2(px[p], a.x, ffma2(py[p], a.y, ffma2(pz[p], b.x, b.y)));
            float lo, hi;
            unpack2(t, lo, hi);
            mn[2 * p]     = fminf(mn[2 * p], lo);
            mn[2 * p + 1] = fminf(mn[2 * p + 1], hi);
        }
    }

    #pragma unroll
    for (int i = 0; i < 8; i++) {
        float m = fmaxf(mn[i] + qq[i], 0.0f);
        atomicMin(&om[q0 + i * 256], __float_as_uint(m));
    }
}

// Single block, one deterministic weighted tree reduction.
__global__ void __launch_bounds__(1024) reduce_kernel(const float* __restrict__ pc1_3) {
    __shared__ float sh[1024];
    int t = threadIdx.x;
    float acc = 0.f;

    const float wA  = 0.5f / (float)NA;
    const float wB  = 0.5f / (float)NB;
    const float wSA = 1.0f / (float)NSA;
    const float wSB = 1.0f / (float)NB;
    const float wC  = 1.0f / (float)NC;

    for (int i = t; i < NA; i += 1024)  acc += wA  * sqrtf(__uint_as_float(g_minA[i]));
    for (int i = t; i < NB; i += 1024)  acc += wB  * sqrtf(__uint_as_float(g_minB[i]));
    for (int i = t; i < NB; i += 1024)  acc += wSB * sqrtf(__uint_as_float(g_minSB[i]));
    for (int i = t; i < NSA; i += 1024) acc += wSA * sqrtf(__uint_as_float(g_minSA[i]));
    for (int i = t; i < NC; i += 1024) {
        float d = sqrtf(__uint_as_float(g_minC[i]));
        float df = pc1_3[i] - expf(-d);
        acc += wC * df * df;
    }

    sh[t] = acc;
    __syncthreads();
    for (int s = 512; s > 0; s >>= 1) {
        if (t < s) sh[t] += sh[t + s];
        __syncthreads();
    }
    if (t == 0) g_scalarC = sh[0];
}

// out[b,n,m] = C + 0.5*dist(pc1_0[b,n], pc2[b,m])
// Block tile: 64 rows x 128 cols, 256 threads; each thread 8 rows x 4 cols,
// refs held in registers. grid (16, 32, 4).
__global__ void __launch_bounds__(256) emd_kernel(
    const float* __restrict__ pc1_0, const float* __restrict__ pc2,
    float* __restrict__ out)
{
    __shared__ float4 sP[128];  // (-2x,-2y,-2z,|r|^2) per col
    __shared__ float4 sQ[64];   // (qx,qy,qz,qq) per row
    int b = blockIdx.z;
    const float* Qb = pc1_0 + (size_t)b * Nn * 3;
    const float* Rb = pc2   + (size_t)b * Mm * 3;
    int tid = threadIdx.x;

    if (tid < 128) {
        int m = blockIdx.x * 128 + tid;
        float rx = Rb[m * 3 + 0];
        float ry = Rb[m * 3 + 1];
        float rz = Rb[m * 3 + 2];
        sP[tid] = make_float4(-2.0f * rx, -2.0f * ry, -2.0f * rz,
                              rx * rx + ry * ry + rz * rz);
    } else if (tid < 192) {
        int r = tid - 128;
        int row = blockIdx.y * 64 + r;
        float qx = Qb[row * 3 + 0];
        float qy = Qb[row * 3 + 1];
        float qz = Qb[row * 3 + 2];
        sQ[r] = make_float4(qx, qy, qz, qx * qx + qy * qy + qz * qz);
    }
    __syncthreads();

    float C = g_scalarC;
    int warp = tid >> 5;
    int lane = tid & 31;
    int ml = lane * 4;

    float4 a  = sP[ml + 0];
    float4 bb = sP[ml + 1];
    float4 c  = sP[ml + 2];
    float4 e  = sP[ml + 3];

    size_t rowBase = ((size_t)(b * Nn) + blockIdx.y * 64 + warp * 8) * Mm
                     + blockIdx.x * 128 + ml;

    #pragma unroll 8
    for (int r = 0; r < 8; r++) {
        float4 qv = sQ[warp * 8 + r];  // warp-uniform broadcast
        float d0 = qv.w + fmaf(qv.x, a.x,  fmaf(qv.y, a.y,  fmaf(qv.z, a.z,  a.w)));
        float d1 = qv.w + fmaf(qv.x, bb.x, fmaf(qv.y, bb.y, fmaf(qv.z, bb.z, bb.w)));
        float d2 = qv.w + fmaf(qv.x, c.x,  fmaf(qv.y, c.y,  fmaf(qv.z, c.z,  c.w)));
        float d3 = qv.w + fmaf(qv.x, e.x,  fmaf(qv.y, e.y,  fmaf(qv.z, e.z,  e.w)));
        d0 = fmaxf(d0, 1e-30f);
        d1 = fmaxf(d1, 1e-30f);
        d2 = fmaxf(d2, 1e-30f);
        d3 = fmaxf(d3, 1e-30f);
        float4 o;
        o.x = fmaf(0.5f, d0 * rsqrtf(d0), C);
        o.y = fmaf(0.5f, d1 * rsqrtf(d1), C);
        o.z = fmaf(0.5f, d2 * rsqrtf(d2), C);
        o.w = fmaf(0.5f, d3 * rsqrtf(d3), C);
        *reinterpret_cast<float4*>(&out[rowBase + (size_t)r * Mm]) = o;
    }
}

extern "C" void kernel_launch(void* const* d_in, const int* in_sizes, int n_in,
                              void* d_out, int out_size) {
    const float* pc1_0 = (const float*)d_in[0];  // [4,2048,3]
    const float* pc1_1 = (const float*)d_in[1];  // [4,1024,3]
    const float* pc1_3 = (const float*)d_in[2];  // [4,2048,1]
    const float* pc2   = (const float*)d_in[3];  // [4,2048,3]
    const float* pc3   = (const float*)d_in[4];  // [4,2048,3]
    float* out = (float*)d_out;                  // [4,2048,2048]

    init_kernel<<<32, 256>>>();
    nn_mega<<<208, 256>>>(pc1_0, pc1_1, pc2, pc3);
    reduce_kernel<<<1, 1024>>>(pc1_3);
    emd_kernel<<<dim3(Mm / 128, Nn / 64, Bx), 256>>>(pc1_0, pc2, out);
}

// round 12
// speedup vs baseline: 3.1436x; 1.5050x over previous
#include <cuda_runtime.h>
#include <math.h>

#define Bx 4
#define Nn 2048
#define Mm 2048
#define Pp 2048
#define NSs 1024
#define NA (Bx*Nn)    // 8192
#define NB (Bx*Mm)    // 8192
#define NSA (Bx*NSs)  // 4096
#define NC (Bx*Pp)    // 8192

#define RC 256        // refs per block chunk

typedef unsigned long long ull;

// Partial per-chunk minima (atomic-free; every slot written exactly once).
__device__ float g_pA[32 * NA];        // [rc][q]
__device__ float g_pB[32 * NB];
__device__ float g_pSA[32 * NSA];
__device__ float g_pSB[16 * NB];
__device__ float g_pC[Bx * 8 * Pp];    // [b][rc][q]
__device__ float g_bsum[160];          // reduce1 partials (144 used)
__device__ float g_scalarC;

__device__ __forceinline__ ull pack2(float lo, float hi) {
    ull r;
    asm("mov.b64 %0, {%1, %2};" : "=l"(r) : "f"(lo), "f"(hi));
    return r;
}
__device__ __forceinline__ void unpack2(ull v, float& lo, float& hi) {
    asm("mov.b64 {%0, %1}, %2;" : "=f"(lo), "=f"(hi) : "l"(v));
}
__device__ __forceinline__ ull ffma2(ull a, ull b, ull c) {
    ull d;
    asm("fma.rn.f32x2 %0, %1, %2, %3;" : "=l"(d) : "l"(a), "l"(b), "l"(c));
    return d;
}

// All 5 NN tasks, one launch, 416 uniform blocks.
// Every block: 2048 queries (8/thread, 4 f32x2 packs) x 256 refs.
//   [0,128):   A  qb=bi>>5 (4), rc=bi&31 (32)  pc1_0 vs pc2   -> g_pA[rc*8192+q]
//   [128,256): B  qb=bi>>5,     rc=bi&31       pc2 vs pc1_0   -> g_pB
//   [256,320): SA qb=bi>>5 (2), rc=bi&31       pc1_1 vs pc2   -> g_pSA[rc*4096+q]
//   [320,384): SB qb=bi>>4 (4), rc=bi&15 (16)  pc2 vs pc1_1   -> g_pSB[rc*8192+q]
//   [384,416): C  b=bi>>3 (4),  rc=bi&7  (8)   pc3[b] vs pc2[b] -> g_pC[b*16384+rc*2048+q]
__global__ void __launch_bounds__(256) nn_mega(
    const float* __restrict__ pc1_0, const float* __restrict__ pc1_1,
    const float* __restrict__ pc2,   const float* __restrict__ pc3)
{
    // refs duplicated into both f32x2 halves:
    // sA[j] = { (-2x,-2x), (-2y,-2y) }, sB[j] = { (-2z,-2z), (w,w) }
    __shared__ ulonglong2 sA[RC];
    __shared__ ulonglong2 sB[RC];

    const float* Q; const float* R; float* om;
    int qb, rc;
    int bi = blockIdx.x;
    if (bi < 128)      {            qb = bi >> 5; rc = bi & 31;
        Q = pc1_0; R = pc2;   om = g_pA  + rc * NA; }
    else if (bi < 256) { bi -= 128; qb = bi >> 5; rc = bi & 31;
        Q = pc2;   R = pc1_0; om = g_pB  + rc * NB; }
    else if (bi < 320) { bi -= 256; qb = bi >> 5; rc = bi & 31;
        Q = pc1_1; R = pc2;   om = g_pSA + rc * NSA; }
    else if (bi < 384) { bi -= 320; qb = bi >> 4; rc = bi & 15;
        Q = pc2;   R = pc1_1; om = g_pSB + rc * NB; }
    else { bi -= 384; int b = bi >> 3; rc = bi & 7; qb = 0;
        Q = pc3 + b * Pp * 3; R = pc2 + b * Mm * 3;
        om = g_pC + b * 8 * Pp + rc * Pp; }

    // Stage 256 refs (1 per thread).
    {
        int t = threadIdx.x;
        int r = rc * RC + t;
        float rx = R[r * 3 + 0];
        float ry = R[r * 3 + 1];
        float rz = R[r * 3 + 2];
        float w  = rx * rx + ry * ry + rz * rz;
        ulonglong2 a, bb;
        a.x  = pack2(-2.0f * rx, -2.0f * rx);
        a.y  = pack2(-2.0f * ry, -2.0f * ry);
        bb.x = pack2(-2.0f * rz, -2.0f * rz);
        bb.y = pack2(w, w);
        sA[t] = a;
        sB[t] = bb;
    }

    // 8 queries per thread: q_i = qb*2048 + i*256 + tid (coalesced).
    int q0 = qb * 2048 + threadIdx.x;
    float qq[8];
    ull px[4], py[4], pz[4];
    #pragma unroll
    for (int p = 0; p < 4; p++) {
        int qa = q0 + (2 * p) * 256;
        int qc = q0 + (2 * p + 1) * 256;
        float ax = Q[qa * 3 + 0], ay = Q[qa * 3 + 1], az = Q[qa * 3 + 2];
        float cx = Q[qc * 3 + 0], cy = Q[qc * 3 + 1], cz = Q[qc * 3 + 2];
        qq[2 * p]     = ax * ax + ay * ay + az * az;
        qq[2 * p + 1] = cx * cx + cy * cy + cz * cz;
        px[p] = pack2(ax, cx);
        py[p] = pack2(ay, cy);
        pz[p] = pack2(az, cz);
    }

    __syncthreads();

    // d' = w - 2 q.r  (qq added after the min)
    float mn[8];
    #pragma unroll
    for (int i = 0; i < 8; i++) mn[i] = 3.0e38f;

    #pragma unroll 4
    for (int j = 0; j < RC; j++) {
        ulonglong2 a = sA[j];   // (xx, yy)
        ulonglong2 b = sB[j];   // (zz, ww)
        #pragma unroll
        for (int p = 0; p < 4; p++) {
            ull t = ffma2(px[p], a.x, ffma2(py[p], a.y, ffma2(pz[p], b.x, b.y)));
            float lo, hi;
            unpack2(t, lo, hi);
            mn[2 * p]     = fminf(mn[2 * p], lo);
            mn[2 * p + 1] = fminf(mn[2 * p + 1], hi);
        }
    }

    #pragma unroll
    for (int i = 0; i < 8; i++) {
        om[q0 + i * 256] = fmaxf(mn[i] + qq[i], 0.0f);   // plain store, no atomic
    }
}

// reduce1: 144 blocks x 256 threads, 1 thread per query (36864 total).
// Min over ref-chunks, transform, weighted block sum -> g_bsum[bid].
__global__ void __launch_bounds__(256) reduce1_kernel(const float* __restrict__ pc1_3) {
    int i = blockIdx.x * 256 + threadIdx.x;
    float val;
    if (i < 8192) {                       // A: dist2 of main chamfer
        float m = 3.0e38f;
        #pragma unroll
        for (int rcs = 0; rcs < 32; rcs++) m = fminf(m, g_pA[rcs * NA + i]);
        val = (0.5f / (float)NA) * sqrtf(m);
    } else if (i < 16384) {               // B
        int q = i - 8192;
        float m = 3.0e38f;
        #pragma unroll
        for (int rcs = 0; rcs < 32; rcs++) m = fminf(m, g_pB[rcs * NB + q]);
        val = (0.5f / (float)NB) * sqrtf(m);
    } else if (i < 20480) {               // SA
        int q = i - 16384;
        float m = 3.0e38f;
        #pragma unroll
        for (int rcs = 0; rcs < 32; rcs++) m = fminf(m, g_pSA[rcs * NSA + q]);
        val = (1.0f / (float)NSA) * sqrtf(m);
    } else if (i < 28672) {               // SB
        int q = i - 20480;
        float m = 3.0e38f;
        #pragma unroll
        for (int rcs = 0; rcs < 16; rcs++) m = fminf(m, g_pSB[rcs * NB + q]);
        val = (1.0f / (float)NB) * sqrtf(m);
    } else {                              // C (confidence)
        int qi = i - 28672;               // 0..8191
        int b = qi >> 11, q = qi & 2047;
        float m = 3.0e38f;
        #pragma unroll
        for (int rcs = 0; rcs < 8; rcs++) m = fminf(m, g_pC[b * 8 * Pp + rcs * Pp + q]);
        float df = pc1_3[qi] - expf(-sqrtf(m));
        val = (1.0f / (float)NC) * df * df;
    }

    __shared__ float sh[256];
    int t = threadIdx.x;
    sh[t] = val;
    __syncthreads();
    for (int s = 128; s > 0; s >>= 1) {
        if (t < s) sh[t] += sh[t + s];
        __syncthreads();
    }
    if (t == 0) g_bsum[blockIdx.x] = sh[0];
}

// reduce2: fold 144 block partials deterministically.
__global__ void __launch_bounds__(256) reduce2_kernel() {
    __shared__ float sh[256];
    int t = threadIdx.x;
    sh[t] = (t < 144) ? g_bsum[t] : 0.0f;
    __syncthreads();
    for (int s = 128; s > 0; s >>= 1) {
        if (t < s) sh[t] += sh[t + s];
        __syncthreads();
    }
    if (t == 0) g_scalarC = sh[0];
}

// out[b,n,m] = C + 0.5*dist(pc1_0[b,n], pc2[b,m])
// Block tile: 64 rows x 128 cols, 256 threads; each thread 8 rows x 4 cols.
__global__ void __launch_bounds__(256) emd_kernel(
    const float* __restrict__ pc1_0, const float* __restrict__ pc2,
    float* __restrict__ out)
{
    __shared__ float4 sP[128];  // (-2x,-2y,-2z,|r|^2) per col
    __shared__ float4 sQ[64];   // (qx,qy,qz,qq) per row
    int b = blockIdx.z;
    const float* Qb = pc1_0 + (size_t)b * Nn * 3;
    const float* Rb = pc2   + (size_t)b * Mm * 3;
    int tid = threadIdx.x;

    if (tid < 128) {
        int m = blockIdx.x * 128 + tid;
        float rx = Rb[m * 3 + 0];
        float ry = Rb[m * 3 + 1];
        float rz = Rb[m * 3 + 2];
        sP[tid] = make_float4(-2.0f * rx, -2.0f * ry, -2.0f * rz,
                              rx * rx + ry * ry + rz * rz);
    } else if (tid < 192) {
        int r = tid - 128;
        int row = blockIdx.y * 64 + r;
        float qx = Qb[row * 3 + 0];
        float qy = Qb[row * 3 + 1];
        float qz = Qb[row * 3 + 2];
        sQ[r] = make_float4(qx, qy, qz, qx * qx + qy * qy + qz * qz);
    }
    __syncthreads();

    float C = g_scalarC;
    int warp = tid >> 5;
    int lane = tid & 31;
    int ml = lane * 4;

    float4 a  = sP[ml + 0];
    float4 bb = sP[ml + 1];
    float4 c  = sP[ml + 2];
    float4 e  = sP[ml + 3];

    size_t rowBase = ((size_t)(b * Nn) + blockIdx.y * 64 + warp * 8) * Mm
                     + blockIdx.x * 128 + ml;

    #pragma unroll 8
    for (int r = 0; r < 8; r++) {
        float4 qv = sQ[warp * 8 + r];  // warp-uniform broadcast
        float d0 = qv.w + fmaf(qv.x, a.x,  fmaf(qv.y, a.y,  fmaf(qv.z, a.z,  a.w)));
        float d1 = qv.w + fmaf(qv.x, bb.x, fmaf(qv.y, bb.y, fmaf(qv.z, bb.z, bb.w)));
        float d2 = qv.w + fmaf(qv.x, c.x,  fmaf(qv.y, c.y,  fmaf(qv.z, c.z,  c.w)));
        float d3 = qv.w + fmaf(qv.x, e.x,  fmaf(qv.y, e.y,  fmaf(qv.z, e.z,  e.w)));
        d0 = fmaxf(d0, 1e-30f);
        d1 = fmaxf(d1, 1e-30f);
        d2 = fmaxf(d2, 1e-30f);
        d3 = fmaxf(d3, 1e-30f);
        float4 o;
        o.x = fmaf(0.5f, d0 * rsqrtf(d0), C);
        o.y = fmaf(0.5f, d1 * rsqrtf(d1), C);
        o.z = fmaf(0.5f, d2 * rsqrtf(d2), C);
        o.w = fmaf(0.5f, d3 * rsqrtf(d3), C);
        *reinterpret_cast<float4*>(&out[rowBase + (size_t)r * Mm]) = o;
    }
}

extern "C" void kernel_launch(void* const* d_in, const int* in_sizes, int n_in,
                              void* d_out, int out_size) {
    const float* pc1_0 = (const float*)d_in[0];  // [4,2048,3]
    const float* pc1_1 = (const float*)d_in[1];  // [4,1024,3]
    const float* pc1_3 = (const float*)d_in[2];  // [4,2048,1]
    const float* pc2   = (const float*)d_in[3];  // [4,2048,3]
    const float* pc3   = (const float*)d_in[4];  // [4,2048,3]
    float* out = (float*)d_out;                  // [4,2048,2048]

    nn_mega<<<416, 256>>>(pc1_0, pc1_1, pc2, pc3);
    reduce1_kernel<<<144, 256>>>(pc1_3);
    reduce2_kernel<<<1, 256>>>();
    emd_kernel<<<dim3(Mm / 128, Nn / 64, Bx), 256>>>(pc1_0, pc2, out);
}